// round 4
// baseline (speedup 1.0000x reference)
#include <cuda_runtime.h>
#include <cuda_bf16.h>
#include <cstdint>

// Problem constants (fixed shapes from reference setup_inputs)
#define NN 50000      // nodes
#define FF 128        // F_in == H
#define OO 64         // output feature dim
#define EE 800000     // edges per relation (and neg edges)

// ---------------- scratch (device globals; no allocation allowed) ----------
// NOTE: these symbols are referenced ONLY inside device code. Passing them as
// kernel arguments from host code is invalid (host-side shadow address) and
// was the root cause of the rounds 1-3 zero-output failure.
__device__ alignas(16) float g_agg0[NN * FF];     // relation 0 aggregate
__device__ alignas(16) float g_agg1[NN * FF];     // relation 1 aggregate
__device__ alignas(16) float g_h1[NN * FF];       // layer 1 output
__device__ alignas(16) float g_h2[NN * OO];       // layer 2 output
__device__ alignas(16) float g_rdeg[2 * NN];      // degree -> 1/max(deg,1)
__device__ alignas(16) float g_W1[384 * 128];     // packed [Wself_sum; Wn0; Wn1]
__device__ alignas(16) float g_b1[128];
__device__ alignas(16) float g_W2[384 * 64];      // packed layer 2
__device__ alignas(16) float g_b2[64];

// ---------------- small utility kernels ------------------------------------
__global__ void zero_deg_kernel() {
    int i = blockIdx.x * blockDim.x + threadIdx.x;
    if (i < 2 * NN) g_rdeg[i] = 0.0f;
}

__global__ void deg_kernel(const int* __restrict__ edges) {
    int i = blockIdx.x * blockDim.x + threadIdx.x;
    if (i < 2 * EE) {
        int r = i / EE;
        int e = i - r * EE;
        int dst = edges[r * 2 * EE + EE + e];
        atomicAdd(&g_rdeg[r * NN + dst], 1.0f);
    }
}

__global__ void rdeg_kernel() {
    int i = blockIdx.x * blockDim.x + threadIdx.x;
    if (i < 2 * NN) {
        float d = g_rdeg[i];
        g_rdeg[i] = 1.0f / fmaxf(d, 1.0f);
    }
}

// Pack W = [Wself[0]+Wself[1]; Wneigh[0]; Wneigh[1]]  (384 x Fout), bias sum.
// Destination globals selected INSIDE device code (host may not reference them).
template <int LAYER>
__global__ void pack_kernel(const float* __restrict__ Wself,
                            const float* __restrict__ Wneigh,
                            const float* __restrict__ b) {
    constexpr int Fout = (LAYER == 1) ? 128 : 64;
    float* Wout = (LAYER == 1) ? g_W1 : g_W2;
    float* bout = (LAYER == 1) ? g_b1 : g_b2;
    int idx = blockIdx.x * blockDim.x + threadIdx.x;
    constexpr int total = 384 * Fout;
    if (idx < total) {
        int k = idx / Fout;
        int n = idx - k * Fout;
        float w;
        if (k < 128)      w = Wself[k * Fout + n] + Wself[128 * Fout + k * Fout + n];
        else if (k < 256) w = Wneigh[(k - 128) * Fout + n];
        else              w = Wneigh[128 * Fout + (k - 256) * Fout + n];
        Wout[idx] = w;
    }
    if (idx < Fout) bout[idx] = b[idx] + b[Fout + idx];
}

__global__ void zero_aggs_kernel() {
    int i = blockIdx.x * blockDim.x + threadIdx.x;
    int n4 = NN * FF / 4;
    if (i < n4) {
        float4 z = make_float4(0.f, 0.f, 0.f, 0.f);
        reinterpret_cast<float4*>(g_agg0)[i] = z;
        reinterpret_cast<float4*>(g_agg1)[i] = z;
    }
}

// ---------------- scatter-sum (one warp per (relation, edge)) --------------
__global__ void scatter_kernel(const float* __restrict__ feat_ext, int use_h1,
                               const int* __restrict__ edges) {
    int gw = (blockIdx.x * blockDim.x + threadIdx.x) >> 5;
    int lane = threadIdx.x & 31;
    if (gw >= 2 * EE) return;
    int r = gw / EE;
    int e = gw - r * EE;
    const int* ed = edges + r * 2 * EE;
    int src = ed[e];
    int dst = ed[EE + e];
    const float* feat = use_h1 ? g_h1 : feat_ext;
    float4 v = *reinterpret_cast<const float4*>(feat + (size_t)src * FF + lane * 4);
    float* agg = r ? g_agg1 : g_agg0;
    float* p = agg + (size_t)dst * FF + lane * 4;
    atomicAdd(p + 0, v.x);
    atomicAdd(p + 1, v.y);
    atomicAdd(p + 2, v.z);
    atomicAdd(p + 3, v.w);
}

// scale agg rows by 1/max(deg,1) -> mean
__global__ void scale_kernel() {
    int i = blockIdx.x * blockDim.x + threadIdx.x;
    int n4 = NN * FF / 4;
    if (i >= n4) return;
    int row = i >> 5;  // (i*4)/128
    float r0 = g_rdeg[row];
    float r1 = g_rdeg[NN + row];
    float4 a = reinterpret_cast<float4*>(g_agg0)[i];
    a.x *= r0; a.y *= r0; a.z *= r0; a.w *= r0;
    reinterpret_cast<float4*>(g_agg0)[i] = a;
    float4 b = reinterpret_cast<float4*>(g_agg1)[i];
    b.x *= r1; b.y *= r1; b.z *= r1; b.w *= r1;
    reinterpret_cast<float4*>(g_agg1)[i] = b;
}

// ---------------- fused 3-slice SGEMM:  C = [A0|A1|A2] @ W + bias ----------
template <int LAYER>
__global__ void __launch_bounds__(256) gemm_layer(const float* __restrict__ x) {
    constexpr int N  = (LAYER == 1) ? 128 : 64;
    constexpr int BN = N;
    constexpr int TN = (LAYER == 1) ? 8 : 4;
    constexpr int BM = 128, BK = 32, TM = 8;
    constexpr bool RELU = (LAYER == 1);
    constexpr int M = NN;

    __shared__ alignas(16) float As[BK][BM + 4];
    __shared__ alignas(16) float Bs[BK][BN];

    const float* A0   = (LAYER == 1) ? x : g_h1;
    const float* W    = (LAYER == 1) ? g_W1 : g_W2;
    const float* bias = (LAYER == 1) ? g_b1 : g_b2;
    float* C          = (LAYER == 1) ? g_h1 : g_h2;

    const float* Asrc[3] = {A0, g_agg0, g_agg1};

    int tid = threadIdx.x;
    int m0 = blockIdx.x * BM;
    int tx = tid % (BN / TN);
    int ty = tid / (BN / TN);

    float acc[TM][TN];
#pragma unroll
    for (int i = 0; i < TM; i++)
#pragma unroll
        for (int j = 0; j < TN; j++) acc[i][j] = 0.f;

#pragma unroll 1
    for (int t = 0; t < 12; ++t) {
        int kg = t * BK;
        const float* Ap = Asrc[kg >> 7];
        int koff = kg & 127;

        // A tile: 128x32, transposed into As[k][m]
#pragma unroll
        for (int i = 0; i < 4; ++i) {
            int idx = tid + i * 256;   // 0..1023
            int row = idx >> 3;
            int c4 = idx & 7;
            float4 v = make_float4(0.f, 0.f, 0.f, 0.f);
            int gm = m0 + row;
            if (gm < M)
                v = *reinterpret_cast<const float4*>(Ap + (size_t)gm * 128 + koff + c4 * 4);
            As[c4 * 4 + 0][row] = v.x;
            As[c4 * 4 + 1][row] = v.y;
            As[c4 * 4 + 2][row] = v.z;
            As[c4 * 4 + 3][row] = v.w;
        }
        // B tile: 32 x BN
#pragma unroll
        for (int i = 0; i < BN / 32; ++i) {
            int idx = tid + i * 256;
            int kk = idx / (BN / 4);
            int n4 = idx - kk * (BN / 4);
            float4 v = *reinterpret_cast<const float4*>(W + (size_t)(kg + kk) * N + n4 * 4);
            *reinterpret_cast<float4*>(&Bs[kk][n4 * 4]) = v;
        }
        __syncthreads();

#pragma unroll
        for (int kk = 0; kk < BK; ++kk) {
            float a[TM], b[TN];
            const float4* Ar = reinterpret_cast<const float4*>(&As[kk][ty * TM]);
            float4 a0 = Ar[0], a1 = Ar[1];
            a[0] = a0.x; a[1] = a0.y; a[2] = a0.z; a[3] = a0.w;
            a[4] = a1.x; a[5] = a1.y; a[6] = a1.z; a[7] = a1.w;
            const float4* Br = reinterpret_cast<const float4*>(&Bs[kk][tx * TN]);
            float4 b0 = Br[0];
            b[0] = b0.x; b[1] = b0.y; b[2] = b0.z; b[3] = b0.w;
            if (TN == 8) {
                float4 b1 = Br[1];
                b[4] = b1.x; b[5] = b1.y; b[6] = b1.z; b[7] = b1.w;
            }
#pragma unroll
            for (int i = 0; i < TM; i++)
#pragma unroll
                for (int j = 0; j < TN; j++) acc[i][j] += a[i] * b[j];
        }
        __syncthreads();
    }

#pragma unroll
    for (int i = 0; i < TM; i++) {
        int gm = m0 + ty * TM + i;
        if (gm >= M) continue;
#pragma unroll
        for (int j = 0; j < TN; j++) {
            int gn = tx * TN + j;
            float v = acc[i][j] + bias[gn];
            if (RELU) v = fmaxf(v, 0.f);
            C[(size_t)gm * N + gn] = v;
        }
    }
}

// ---------------- edge scoring (warp per edge) ------------------------------
__global__ void score_kernel(const int* __restrict__ edges,
                             const int* __restrict__ neg,
                             float* __restrict__ out, int out_n) {
    int gw = (blockIdx.x * blockDim.x + threadIdx.x) >> 5;
    int lane = threadIdx.x & 31;
    if (gw >= 2 * EE) return;
    int u, v;
    if (gw < EE) { u = edges[gw]; v = edges[EE + gw]; }
    else { int e = gw - EE; u = neg[e]; v = neg[EE + e]; }
    float2 a = *reinterpret_cast<const float2*>(g_h2 + (size_t)u * OO + lane * 2);
    float2 b = *reinterpret_cast<const float2*>(g_h2 + (size_t)v * OO + lane * 2);
    float s = a.x * b.x + a.y * b.y;
#pragma unroll
    for (int off = 16; off; off >>= 1) s += __shfl_xor_sync(0xffffffffu, s, off);
    if (lane == 0 && gw < out_n) out[gw] = s;
}

// ---------------- launch ----------------------------------------------------
extern "C" void kernel_launch(void* const* d_in, const int* in_sizes, int n_in,
                              void* d_out, int out_size) {
    // Resolve inputs by element count; positional fallback (reference order).
    const float* x = nullptr;  const int* edges = nullptr; const int* neg = nullptr;
    const float* Wneigh1 = nullptr, *Wself1 = nullptr, *b1 = nullptr;
    const float* Wneigh2 = nullptr, *Wself2 = nullptr, *b2 = nullptr;
    {
        const float* wn1 = nullptr, *ws1 = nullptr, *wn2 = nullptr, *ws2 = nullptr;
        const float* xx = nullptr, *bb1 = nullptr, *bb2 = nullptr;
        const int* ee = nullptr, *nn = nullptr;
        for (int i = 0; i < n_in; ++i) {
            long s = in_sizes[i];
            const void* p = d_in[i];
            if      (s == (long)NN * FF)       xx = (const float*)p;
            else if (s == (long)2 * 2 * EE)    ee = (const int*)p;
            else if (s == (long)2 * EE)        nn = (const int*)p;
            else if (s == (long)2 * 128 * 128) { if (!wn1) wn1 = (const float*)p; else ws1 = (const float*)p; }
            else if (s == (long)2 * 128)       bb1 = (const float*)p;
            else if (s == (long)2 * 128 * 64)  { if (!wn2) wn2 = (const float*)p; else ws2 = (const float*)p; }
            else if (s == (long)2 * 64)        bb2 = (const float*)p;
        }
        if (xx && ee && nn && wn1 && ws1 && bb1 && wn2 && ws2 && bb2) {
            x = xx; edges = ee; neg = nn;
            Wneigh1 = wn1; Wself1 = ws1; b1 = bb1;
            Wneigh2 = wn2; Wself2 = ws2; b2 = bb2;
        }
    }
    if (!x) {  // positional fallback (reference signature order)
        x       = (const float*)d_in[0];
        edges   = (const int*)  d_in[1];
        neg     = (const int*)  d_in[2];
        Wneigh1 = (const float*)d_in[3];
        Wself1  = (const float*)d_in[4];
        b1      = (const float*)d_in[5];
        Wneigh2 = (const float*)d_in[6];
        Wself2  = (const float*)d_in[7];
        b2      = (const float*)d_in[8];
    }
    float* out = (float*)d_out;
    int out_n = out_size;
    if (out_n > 2 * EE) out_n = 2 * EE;

    // degrees (shared across both layers)
    zero_deg_kernel<<<(2 * NN + 255) / 256, 256>>>();
    deg_kernel<<<(2 * EE + 255) / 256, 256>>>(edges);
    rdeg_kernel<<<(2 * NN + 255) / 256, 256>>>();

    // packed weights (destination globals selected in device code)
    pack_kernel<1><<<(384 * 128 + 255) / 256, 256>>>(Wself1, Wneigh1, b1);
    pack_kernel<2><<<(384 * 64 + 255) / 256, 256>>>(Wself2, Wneigh2, b2);

    int zeroBlocks = (NN * FF / 4 + 255) / 256;
    int scatterBlocks = (2 * EE) / 8;   // warp per (rel, edge), 8 warps/block
    int gemmBlocks = (NN + 127) / 128;

    // layer 1
    zero_aggs_kernel<<<zeroBlocks, 256>>>();
    scatter_kernel<<<scatterBlocks, 256>>>(x, 0, edges);
    scale_kernel<<<zeroBlocks, 256>>>();
    gemm_layer<1><<<gemmBlocks, 256>>>(x);

    // layer 2
    zero_aggs_kernel<<<zeroBlocks, 256>>>();
    scatter_kernel<<<scatterBlocks, 256>>>(nullptr, 1, edges);
    scale_kernel<<<zeroBlocks, 256>>>();
    gemm_layer<2><<<gemmBlocks, 256>>>(nullptr);

    // scoring
    score_kernel<<<scatterBlocks, 256>>>(edges, neg, out, out_n);
}

// round 5
// speedup vs baseline: 1.8035x; 1.8035x over previous
#include <cuda_runtime.h>
#include <cuda_bf16.h>
#include <cstdint>

// Problem constants (fixed shapes from reference setup_inputs)
#define NN 50000      // nodes
#define FF 128        // F_in == H
#define OO 64        // output feature dim
#define EE 800000     // edges per relation (and neg edges)

// ---------------- scratch (device globals; device-code access ONLY) --------
__device__ alignas(16) float g_agg0[NN * FF];
__device__ alignas(16) float g_agg1[NN * FF];
__device__ alignas(16) float g_h1[NN * FF];
__device__ alignas(16) float g_h2[NN * OO];
__device__ alignas(16) float g_rdeg[2 * NN];      // degree -> 1/max(deg,1)
__device__ alignas(16) float g_W1[384 * 128];
__device__ alignas(16) float g_b1[128];
__device__ alignas(16) float g_W2[384 * 64];
__device__ alignas(16) float g_b2[64];

// ---------------- small utility kernels ------------------------------------
__global__ void zero_deg_kernel() {
    int i = blockIdx.x * blockDim.x + threadIdx.x;
    if (i < 2 * NN) g_rdeg[i] = 0.0f;
}

__global__ void deg_kernel(const int* __restrict__ edges) {
    int i = blockIdx.x * blockDim.x + threadIdx.x;
    if (i < 2 * EE) {
        int r = i / EE;
        int e = i - r * EE;
        int dst = edges[r * 2 * EE + EE + e];
        atomicAdd(&g_rdeg[r * NN + dst], 1.0f);
    }
}

__global__ void rdeg_kernel() {
    int i = blockIdx.x * blockDim.x + threadIdx.x;
    if (i < 2 * NN) {
        float d = g_rdeg[i];
        g_rdeg[i] = 1.0f / fmaxf(d, 1.0f);
    }
}

// Pack W = [Wself[0]+Wself[1]; Wneigh[0]; Wneigh[1]]  (384 x Fout), bias sum.
template <int LAYER>
__global__ void pack_kernel(const float* __restrict__ Wself,
                            const float* __restrict__ Wneigh,
                            const float* __restrict__ b) {
    constexpr int Fout = (LAYER == 1) ? 128 : 64;
    float* Wout = (LAYER == 1) ? g_W1 : g_W2;
    float* bout = (LAYER == 1) ? g_b1 : g_b2;
    int idx = blockIdx.x * blockDim.x + threadIdx.x;
    constexpr int total = 384 * Fout;
    if (idx < total) {
        int k = idx / Fout;
        int n = idx - k * Fout;
        float w;
        if (k < 128)      w = Wself[k * Fout + n] + Wself[128 * Fout + k * Fout + n];
        else if (k < 256) w = Wneigh[(k - 128) * Fout + n];
        else              w = Wneigh[128 * Fout + (k - 256) * Fout + n];
        Wout[idx] = w;
    }
    if (idx < Fout) bout[idx] = b[idx] + b[Fout + idx];
}

__global__ void zero_aggs_kernel() {
    int i = blockIdx.x * blockDim.x + threadIdx.x;
    int n4 = NN * FF / 4;
    if (i < n4) {
        float4 z = make_float4(0.f, 0.f, 0.f, 0.f);
        reinterpret_cast<float4*>(g_agg0)[i] = z;
        reinterpret_cast<float4*>(g_agg1)[i] = z;
    }
}

// ---------------- scatter-sum: vectorized red.global.add.v4.f32 ------------
__device__ __forceinline__ void red_add_v4(float* p, float4 v) {
    asm volatile("red.global.add.v4.f32 [%0], {%1, %2, %3, %4};"
                 :: "l"(p), "f"(v.x), "f"(v.y), "f"(v.z), "f"(v.w)
                 : "memory");
}

// one warp per (relation, edge); each lane: 1 LDG.128 + 1 RED.128
__global__ void scatter_kernel(const float* __restrict__ feat_ext, int use_h1,
                               const int* __restrict__ edges) {
    int gw = (blockIdx.x * blockDim.x + threadIdx.x) >> 5;
    int lane = threadIdx.x & 31;
    if (gw >= 2 * EE) return;
    int r = gw / EE;
    int e = gw - r * EE;
    const int* ed = edges + r * 2 * EE;
    int src = ed[e];
    int dst = ed[EE + e];
    const float* feat = use_h1 ? g_h1 : feat_ext;
    float4 v = *reinterpret_cast<const float4*>(feat + (size_t)src * FF + lane * 4);
    float* agg = r ? g_agg1 : g_agg0;
    red_add_v4(agg + (size_t)dst * FF + lane * 4, v);
}

// ---------------- fused 3-slice SGEMM with in-load mean scaling -------------
// C = [A0 | agg0*rdeg0 | agg1*rdeg1] @ W + bias
template <int LAYER>
__global__ void __launch_bounds__(256) gemm_layer(const float* __restrict__ x) {
    constexpr int N  = (LAYER == 1) ? 128 : 64;
    constexpr int BN = N;
    constexpr int TN = (LAYER == 1) ? 8 : 4;
    constexpr int BM = 128, BK = 32, TM = 8;
    constexpr bool RELU = (LAYER == 1);
    constexpr int M = NN;

    __shared__ alignas(16) float As[BK][BM + 4];
    __shared__ alignas(16) float Bs[BK][BN];

    const float* A0   = (LAYER == 1) ? x : g_h1;
    const float* W    = (LAYER == 1) ? g_W1 : g_W2;
    const float* bias = (LAYER == 1) ? g_b1 : g_b2;
    float* C          = (LAYER == 1) ? g_h1 : g_h2;

    const float* Asrc[3] = {A0, g_agg0, g_agg1};

    int tid = threadIdx.x;
    int m0 = blockIdx.x * BM;
    int tx = tid % (BN / TN);
    int ty = tid / (BN / TN);

    float acc[TM][TN];
#pragma unroll
    for (int i = 0; i < TM; i++)
#pragma unroll
        for (int j = 0; j < TN; j++) acc[i][j] = 0.f;

#pragma unroll 1
    for (int t = 0; t < 12; ++t) {
        int kg = t * BK;
        int slice = kg >> 7;            // 0: self features, 1/2: agg slices
        const float* Ap = Asrc[slice];
        int koff = kg & 127;

        // A tile: 128x32, transposed into As[k][m]; agg slices scaled by rdeg
#pragma unroll
        for (int i = 0; i < 4; ++i) {
            int idx = tid + i * 256;   // 0..1023
            int row = idx >> 3;
            int c4 = idx & 7;
            float4 v = make_float4(0.f, 0.f, 0.f, 0.f);
            int gm = m0 + row;
            if (gm < M) {
                v = *reinterpret_cast<const float4*>(Ap + (size_t)gm * 128 + koff + c4 * 4);
                if (slice > 0) {
                    float sc = g_rdeg[(slice - 1) * NN + gm];
                    v.x *= sc; v.y *= sc; v.z *= sc; v.w *= sc;
                }
            }
            As[c4 * 4 + 0][row] = v.x;
            As[c4 * 4 + 1][row] = v.y;
            As[c4 * 4 + 2][row] = v.z;
            As[c4 * 4 + 3][row] = v.w;
        }
        // B tile: 32 x BN
#pragma unroll
        for (int i = 0; i < BN / 32; ++i) {
            int idx = tid + i * 256;
            int kk = idx / (BN / 4);
            int n4 = idx - kk * (BN / 4);
            float4 v = *reinterpret_cast<const float4*>(W + (size_t)(kg + kk) * N + n4 * 4);
            *reinterpret_cast<float4*>(&Bs[kk][n4 * 4]) = v;
        }
        __syncthreads();

#pragma unroll
        for (int kk = 0; kk < BK; ++kk) {
            float a[TM], b[TN];
            const float4* Ar = reinterpret_cast<const float4*>(&As[kk][ty * TM]);
            float4 a0 = Ar[0], a1 = Ar[1];
            a[0] = a0.x; a[1] = a0.y; a[2] = a0.z; a[3] = a0.w;
            a[4] = a1.x; a[5] = a1.y; a[6] = a1.z; a[7] = a1.w;
            const float4* Br = reinterpret_cast<const float4*>(&Bs[kk][tx * TN]);
            float4 b0 = Br[0];
            b[0] = b0.x; b[1] = b0.y; b[2] = b0.z; b[3] = b0.w;
            if (TN == 8) {
                float4 b1 = Br[1];
                b[4] = b1.x; b[5] = b1.y; b[6] = b1.z; b[7] = b1.w;
            }
#pragma unroll
            for (int i = 0; i < TM; i++)
#pragma unroll
                for (int j = 0; j < TN; j++) acc[i][j] += a[i] * b[j];
        }
        __syncthreads();
    }

#pragma unroll
    for (int i = 0; i < TM; i++) {
        int gm = m0 + ty * TM + i;
        if (gm >= M) continue;
#pragma unroll
        for (int j = 0; j < TN; j++) {
            int gn = tx * TN + j;
            float v = acc[i][j] + bias[gn];
            if (RELU) v = fmaxf(v, 0.f);
            C[(size_t)gm * N + gn] = v;
        }
    }
}

// ---------------- edge scoring (16 lanes per edge, float4) ------------------
__global__ void score_kernel(const int* __restrict__ edges,
                             const int* __restrict__ neg,
                             float* __restrict__ out, int out_n) {
    int t = blockIdx.x * blockDim.x + threadIdx.x;
    int ge = t >> 4;                 // edge index (0 .. 2EE-1)
    int lane = t & 15;
    if (ge >= 2 * EE) return;
    int u, v;
    if (ge < EE) { u = edges[ge]; v = edges[EE + ge]; }
    else { int e = ge - EE; u = neg[e]; v = neg[EE + e]; }
    float4 a = *reinterpret_cast<const float4*>(g_h2 + (size_t)u * OO + lane * 4);
    float4 b = *reinterpret_cast<const float4*>(g_h2 + (size_t)v * OO + lane * 4);
    float s = a.x * b.x + a.y * b.y + a.z * b.z + a.w * b.w;
#pragma unroll
    for (int off = 8; off; off >>= 1) s += __shfl_xor_sync(0xffffffffu, s, off);
    if (lane == 0 && ge < out_n) out[ge] = s;
}

// ---------------- launch ----------------------------------------------------
extern "C" void kernel_launch(void* const* d_in, const int* in_sizes, int n_in,
                              void* d_out, int out_size) {
    // Resolve inputs by element count; positional fallback (reference order).
    const float* x = nullptr;  const int* edges = nullptr; const int* neg = nullptr;
    const float* Wneigh1 = nullptr, *Wself1 = nullptr, *b1 = nullptr;
    const float* Wneigh2 = nullptr, *Wself2 = nullptr, *b2 = nullptr;
    {
        const float* wn1 = nullptr, *ws1 = nullptr, *wn2 = nullptr, *ws2 = nullptr;
        const float* xx = nullptr, *bb1 = nullptr, *bb2 = nullptr;
        const int* ee = nullptr, *nn = nullptr;
        for (int i = 0; i < n_in; ++i) {
            long s = in_sizes[i];
            const void* p = d_in[i];
            if      (s == (long)NN * FF)       xx = (const float*)p;
            else if (s == (long)2 * 2 * EE)    ee = (const int*)p;
            else if (s == (long)2 * EE)        nn = (const int*)p;
            else if (s == (long)2 * 128 * 128) { if (!wn1) wn1 = (const float*)p; else ws1 = (const float*)p; }
            else if (s == (long)2 * 128)       bb1 = (const float*)p;
            else if (s == (long)2 * 128 * 64)  { if (!wn2) wn2 = (const float*)p; else ws2 = (const float*)p; }
            else if (s == (long)2 * 64)        bb2 = (const float*)p;
        }
        if (xx && ee && nn && wn1 && ws1 && bb1 && wn2 && ws2 && bb2) {
            x = xx; edges = ee; neg = nn;
            Wneigh1 = wn1; Wself1 = ws1; b1 = bb1;
            Wneigh2 = wn2; Wself2 = ws2; b2 = bb2;
        }
    }
    if (!x) {  // positional fallback (reference signature order)
        x       = (const float*)d_in[0];
        edges   = (const int*)  d_in[1];
        neg     = (const int*)  d_in[2];
        Wneigh1 = (const float*)d_in[3];
        Wself1  = (const float*)d_in[4];
        b1      = (const float*)d_in[5];
        Wneigh2 = (const float*)d_in[6];
        Wself2  = (const float*)d_in[7];
        b2      = (const float*)d_in[8];
    }
    float* out = (float*)d_out;
    int out_n = out_size;
    if (out_n > 2 * EE) out_n = 2 * EE;

    // degrees (shared across both layers; converted to reciprocals once)
    zero_deg_kernel<<<(2 * NN + 255) / 256, 256>>>();
    deg_kernel<<<(2 * EE + 255) / 256, 256>>>(edges);
    rdeg_kernel<<<(2 * NN + 255) / 256, 256>>>();

    // packed weights
    pack_kernel<1><<<(384 * 128 + 255) / 256, 256>>>(Wself1, Wneigh1, b1);
    pack_kernel<2><<<(384 * 64 + 255) / 256, 256>>>(Wself2, Wneigh2, b2);

    int zeroBlocks = (NN * FF / 4 + 255) / 256;
    int scatterBlocks = (2 * EE) / 8;   // warp per (rel, edge), 8 warps/block
    int gemmBlocks = (NN + 127) / 128;
    int scoreBlocks = (2 * EE * 16 + 255) / 256;

    // layer 1 (mean-scaling fused into GEMM A-load)
    zero_aggs_kernel<<<zeroBlocks, 256>>>();
    scatter_kernel<<<scatterBlocks, 256>>>(x, 0, edges);
    gemm_layer<1><<<gemmBlocks, 256>>>(x);

    // layer 2
    zero_aggs_kernel<<<zeroBlocks, 256>>>();
    scatter_kernel<<<scatterBlocks, 256>>>(nullptr, 1, edges);
    gemm_layer<2><<<gemmBlocks, 256>>>(nullptr);

    // scoring
    score_kernel<<<scoreBlocks, 256>>>(edges, neg, out, out_n);
}

// round 6
// speedup vs baseline: 2.0901x; 1.1589x over previous
#include <cuda_runtime.h>
#include <cuda_bf16.h>
#include <cstdint>

// Problem constants (fixed shapes from reference setup_inputs)
#define NN 50000      // nodes
#define FF 128        // F_in == H
#define OO 64         // output feature dim
#define EE 800000     // edges per relation (and neg edges)

// ---------------- scratch (device globals; device-code access ONLY) --------
__device__ alignas(16) float g_agg0[NN * FF];     // layer1: 128-wide; layer2: 64-wide
__device__ alignas(16) float g_agg1[NN * FF];
__device__ alignas(16) float g_h1[NN * FF];       // layer 1 output
__device__ alignas(16) float g_Y[NN * FF];        // h1 @ [Wn2_0 | Wn2_1]
__device__ alignas(16) float g_h2[NN * OO];       // layer 2 output
__device__ alignas(16) float g_rdeg[2 * NN];      // degree -> 1/max(deg,1)
__device__ alignas(16) float g_W1[384 * 128];     // packed [Wself_sum; Wn0; Wn1]
__device__ alignas(16) float g_b1[128];
__device__ alignas(16) float g_Wn2pack[128 * 128]; // [Wn2_0 | Wn2_1] (K x 2*O)
__device__ alignas(16) float g_Ws2sum[128 * 64];   // Wself2[0]+Wself2[1]
__device__ alignas(16) float g_b2[64];

// ---------------- zero / degree kernels -------------------------------------
__global__ void zero_all_kernel() {
    int i = blockIdx.x * blockDim.x + threadIdx.x;
    int n4 = NN * FF / 4;
    if (i < n4) {
        float4 z = make_float4(0.f, 0.f, 0.f, 0.f);
        reinterpret_cast<float4*>(g_agg0)[i] = z;
        reinterpret_cast<float4*>(g_agg1)[i] = z;
    }
    if (i < 2 * NN) g_rdeg[i] = 0.0f;
}

__global__ void deg_kernel(const int* __restrict__ edges) {
    int i = blockIdx.x * blockDim.x + threadIdx.x;
    if (i < 2 * EE) {
        int r = i / EE;
        int e = i - r * EE;
        int dst = edges[r * 2 * EE + EE + e];
        atomicAdd(&g_rdeg[r * NN + dst], 1.0f);
    }
}

__global__ void rdeg_kernel() {
    int i = blockIdx.x * blockDim.x + threadIdx.x;
    if (i < 2 * NN) {
        float d = g_rdeg[i];
        g_rdeg[i] = 1.0f / fmaxf(d, 1.0f);
    }
}

// Pack layer1: W1 = [Wself1[0]+Wself1[1]; Wn1[0]; Wn1[1]] (384x128), b1 sum.
__global__ void pack1_kernel(const float* __restrict__ Wself,
                             const float* __restrict__ Wneigh,
                             const float* __restrict__ b) {
    int idx = blockIdx.x * blockDim.x + threadIdx.x;
    if (idx < 384 * 128) {
        int k = idx >> 7;
        int n = idx & 127;
        float w;
        if (k < 128)      w = Wself[k * 128 + n] + Wself[128 * 128 + k * 128 + n];
        else if (k < 256) w = Wneigh[(k - 128) * 128 + n];
        else              w = Wneigh[128 * 128 + (k - 256) * 128 + n];
        g_W1[idx] = w;
    }
    if (idx < 128) g_b1[idx] = b[idx] + b[128 + idx];
}

// Pack layer2: Wn2pack = [Wn2_0 | Wn2_1] (128x128), Ws2sum (128x64), b2 sum.
__global__ void pack2_kernel(const float* __restrict__ Wself,
                             const float* __restrict__ Wneigh,
                             const float* __restrict__ b) {
    int idx = blockIdx.x * blockDim.x + threadIdx.x;
    if (idx < 128 * 128) {
        int k = idx >> 7;
        int n = idx & 127;
        g_Wn2pack[idx] = (n < 64) ? Wneigh[k * 64 + n]
                                  : Wneigh[128 * 64 + k * 64 + (n - 64)];
    }
    if (idx < 128 * 64) g_Ws2sum[idx] = Wself[idx] + Wself[128 * 64 + idx];
    if (idx < 64)       g_b2[idx] = b[idx] + b[64 + idx];
}

__global__ void zero_aggs64_kernel() {
    int i = blockIdx.x * blockDim.x + threadIdx.x;
    int n4 = NN * OO / 4;
    if (i < n4) {
        float4 z = make_float4(0.f, 0.f, 0.f, 0.f);
        reinterpret_cast<float4*>(g_agg0)[i] = z;
        reinterpret_cast<float4*>(g_agg1)[i] = z;
    }
}

// ---------------- vectorized global reduction --------------------------------
__device__ __forceinline__ void red_add_v4(float* p, float4 v) {
    asm volatile("red.global.add.v4.f32 [%0], {%1, %2, %3, %4};"
                 :: "l"(p), "f"(v.x), "f"(v.y), "f"(v.z), "f"(v.w)
                 : "memory");
}

// layer-1 scatter: one warp per (relation, edge); 128-wide x rows
__global__ void scatter_kernel(const float* __restrict__ x,
                               const int* __restrict__ edges) {
    int gw = (blockIdx.x * blockDim.x + threadIdx.x) >> 5;
    int lane = threadIdx.x & 31;
    if (gw >= 2 * EE) return;
    int r = gw / EE;
    int e = gw - r * EE;
    const int* ed = edges + r * 2 * EE;
    int src = ed[e];
    int dst = ed[EE + e];
    float4 v = *reinterpret_cast<const float4*>(x + (size_t)src * FF + lane * 4);
    float* agg = r ? g_agg1 : g_agg0;
    red_add_v4(agg + (size_t)dst * FF + lane * 4, v);
}

// layer-2 scatter: 16 lanes per (relation, edge); 64-wide Y slices
__global__ void scatter2_kernel(const int* __restrict__ edges) {
    int t = blockIdx.x * blockDim.x + threadIdx.x;
    int ge = t >> 4;
    int lane = t & 15;
    if (ge >= 2 * EE) return;
    int r = ge / EE;
    int e = ge - r * EE;
    const int* ed = edges + r * 2 * EE;
    int src = ed[e];
    int dst = ed[EE + e];
    // Y row: [y0 (64) | y1 (64)]; take the slice for this relation
    float4 v = *reinterpret_cast<const float4*>(g_Y + (size_t)src * FF + r * OO + lane * 4);
    float* agg = r ? g_agg1 : g_agg0;
    red_add_v4(agg + (size_t)dst * OO + lane * 4, v);
}

// ---------------- GEMM core (3 modes) ---------------------------------------
// MODE 1: h1 = relu([x | agg0*rdeg0 | agg1*rdeg1] @ W1 + b1)   (K=384, N=128)
// MODE 3: Y  = h1 @ Wn2pack                                     (K=128, N=128)
// MODE 2: h2 = h1 @ Ws2sum + b2 + rdeg0*agg0 + rdeg1*agg1       (K=128, N=64)
template <int MODE>
__global__ void __launch_bounds__(256) gemm_k(const float* __restrict__ x) {
    constexpr int N  = (MODE == 2) ? 64 : 128;
    constexpr int BN = N;
    constexpr int TN = N / 16;          // 8 or 4
    constexpr int BM = 128, BK = 32, TM = 8;
    constexpr int KT = (MODE == 1) ? 12 : 4;
    constexpr int M = NN;

    __shared__ alignas(16) float As[BK][BM + 4];
    __shared__ alignas(16) float Bs[BK][BN];

    const float* A0   = (MODE == 1) ? x : g_h1;
    const float* W    = (MODE == 1) ? g_W1 : ((MODE == 3) ? g_Wn2pack : g_Ws2sum);
    float* C          = (MODE == 1) ? g_h1 : ((MODE == 3) ? g_Y : g_h2);

    int tid = threadIdx.x;
    int m0 = blockIdx.x * BM;
    int tx = tid % (BN / TN);
    int ty = tid / (BN / TN);

    float acc[TM][TN];
#pragma unroll
    for (int i = 0; i < TM; i++)
#pragma unroll
        for (int j = 0; j < TN; j++) acc[i][j] = 0.f;

#pragma unroll 1
    for (int t = 0; t < KT; ++t) {
        int kg = t * BK;
        const float* Ap;
        int slice = 0, koff;
        if (MODE == 1) {
            slice = kg >> 7;
            Ap = (slice == 0) ? A0 : ((slice == 1) ? g_agg0 : g_agg1);
            koff = kg & 127;
        } else {
            Ap = A0;
            koff = kg;
        }

        // A tile: 128x32 transposed into As[k][m]; agg slices scaled by rdeg
#pragma unroll
        for (int i = 0; i < 4; ++i) {
            int idx = tid + i * 256;
            int row = idx >> 3;
            int c4 = idx & 7;
            float4 v = make_float4(0.f, 0.f, 0.f, 0.f);
            int gm = m0 + row;
            if (gm < M) {
                v = *reinterpret_cast<const float4*>(Ap + (size_t)gm * 128 + koff + c4 * 4);
                if (MODE == 1 && slice > 0) {
                    float sc = g_rdeg[(slice - 1) * NN + gm];
                    v.x *= sc; v.y *= sc; v.z *= sc; v.w *= sc;
                }
            }
            As[c4 * 4 + 0][row] = v.x;
            As[c4 * 4 + 1][row] = v.y;
            As[c4 * 4 + 2][row] = v.z;
            As[c4 * 4 + 3][row] = v.w;
        }
        // B tile: 32 x BN
#pragma unroll
        for (int i = 0; i < BN / 32; ++i) {
            int idx = tid + i * 256;
            int kk = idx / (BN / 4);
            int n4 = idx - kk * (BN / 4);
            float4 v = *reinterpret_cast<const float4*>(W + (size_t)(kg + kk) * N + n4 * 4);
            *reinterpret_cast<float4*>(&Bs[kk][n4 * 4]) = v;
        }
        __syncthreads();

#pragma unroll
        for (int kk = 0; kk < BK; ++kk) {
            float a[TM], b[TN];
            const float4* Ar = reinterpret_cast<const float4*>(&As[kk][ty * TM]);
            float4 a0 = Ar[0], a1 = Ar[1];
            a[0] = a0.x; a[1] = a0.y; a[2] = a0.z; a[3] = a0.w;
            a[4] = a1.x; a[5] = a1.y; a[6] = a1.z; a[7] = a1.w;
            const float4* Br = reinterpret_cast<const float4*>(&Bs[kk][tx * TN]);
            float4 b0 = Br[0];
            b[0] = b0.x; b[1] = b0.y; b[2] = b0.z; b[3] = b0.w;
            if (TN == 8) {
                float4 b1 = Br[1];
                b[4] = b1.x; b[5] = b1.y; b[6] = b1.z; b[7] = b1.w;
            }
#pragma unroll
            for (int i = 0; i < TM; i++)
#pragma unroll
                for (int j = 0; j < TN; j++) acc[i][j] += a[i] * b[j];
        }
        __syncthreads();
    }

#pragma unroll
    for (int i = 0; i < TM; i++) {
        int gm = m0 + ty * TM + i;
        if (gm >= M) continue;
        if (MODE == 2) {
            // TN == 4, gn = tx*4 .. tx*4+3 contiguous: vector epilogue
            float r0 = g_rdeg[gm];
            float r1 = g_rdeg[NN + gm];
            float4 a0 = *reinterpret_cast<const float4*>(g_agg0 + (size_t)gm * OO + tx * 4);
            float4 a1 = *reinterpret_cast<const float4*>(g_agg1 + (size_t)gm * OO + tx * 4);
            float4 o;
            o.x = acc[i][0] + g_b2[tx * 4 + 0] + r0 * a0.x + r1 * a1.x;
            o.y = acc[i][1] + g_b2[tx * 4 + 1] + r0 * a0.y + r1 * a1.y;
            o.z = acc[i][2] + g_b2[tx * 4 + 2] + r0 * a0.z + r1 * a1.z;
            o.w = acc[i][3] + g_b2[tx * 4 + 3] + r0 * a0.w + r1 * a1.w;
            *reinterpret_cast<float4*>(g_h2 + (size_t)gm * OO + tx * 4) = o;
        } else {
#pragma unroll
            for (int j = 0; j < TN; j++) {
                int gn = tx * TN + j;
                float v = acc[i][j];
                if (MODE == 1) v = fmaxf(v + g_b1[gn], 0.f);
                C[(size_t)gm * N + gn] = v;
            }
        }
    }
}

// ---------------- edge scoring (16 lanes per edge, float4) ------------------
__global__ void score_kernel(const int* __restrict__ edges,
                             const int* __restrict__ neg,
                             float* __restrict__ out, int out_n) {
    int t = blockIdx.x * blockDim.x + threadIdx.x;
    int ge = t >> 4;
    int lane = t & 15;
    if (ge >= 2 * EE) return;
    int u, v;
    if (ge < EE) { u = edges[ge]; v = edges[EE + ge]; }
    else { int e = ge - EE; u = neg[e]; v = neg[EE + e]; }
    float4 a = *reinterpret_cast<const float4*>(g_h2 + (size_t)u * OO + lane * 4);
    float4 b = *reinterpret_cast<const float4*>(g_h2 + (size_t)v * OO + lane * 4);
    float s = a.x * b.x + a.y * b.y + a.z * b.z + a.w * b.w;
#pragma unroll
    for (int off = 8; off; off >>= 1) s += __shfl_xor_sync(0xffffffffu, s, off);
    if (lane == 0 && ge < out_n) out[ge] = s;
}

// ---------------- launch ----------------------------------------------------
extern "C" void kernel_launch(void* const* d_in, const int* in_sizes, int n_in,
                              void* d_out, int out_size) {
    // Resolve inputs by element count; positional fallback (reference order).
    const float* x = nullptr;  const int* edges = nullptr; const int* neg = nullptr;
    const float* Wneigh1 = nullptr, *Wself1 = nullptr, *b1 = nullptr;
    const float* Wneigh2 = nullptr, *Wself2 = nullptr, *b2 = nullptr;
    {
        const float* wn1 = nullptr, *ws1 = nullptr, *wn2 = nullptr, *ws2 = nullptr;
        const float* xx = nullptr, *bb1 = nullptr, *bb2 = nullptr;
        const int* ee = nullptr, *nn = nullptr;
        for (int i = 0; i < n_in; ++i) {
            long s = in_sizes[i];
            const void* p = d_in[i];
            if      (s == (long)NN * FF)       xx = (const float*)p;
            else if (s == (long)2 * 2 * EE)    ee = (const int*)p;
            else if (s == (long)2 * EE)        nn = (const int*)p;
            else if (s == (long)2 * 128 * 128) { if (!wn1) wn1 = (const float*)p; else ws1 = (const float*)p; }
            else if (s == (long)2 * 128)       bb1 = (const float*)p;
            else if (s == (long)2 * 128 * 64)  { if (!wn2) wn2 = (const float*)p; else ws2 = (const float*)p; }
            else if (s == (long)2 * 64)        bb2 = (const float*)p;
        }
        if (xx && ee && nn && wn1 && ws1 && bb1 && wn2 && ws2 && bb2) {
            x = xx; edges = ee; neg = nn;
            Wneigh1 = wn1; Wself1 = ws1; b1 = bb1;
            Wneigh2 = wn2; Wself2 = ws2; b2 = bb2;
        }
    }
    if (!x) {  // positional fallback (reference signature order)
        x       = (const float*)d_in[0];
        edges   = (const int*)  d_in[1];
        neg     = (const int*)  d_in[2];
        Wneigh1 = (const float*)d_in[3];
        Wself1  = (const float*)d_in[4];
        b1      = (const float*)d_in[5];
        Wneigh2 = (const float*)d_in[6];
        Wself2  = (const float*)d_in[7];
        b2      = (const float*)d_in[8];
    }
    float* out = (float*)d_out;
    int out_n = out_size;
    if (out_n > 2 * EE) out_n = 2 * EE;

    int zeroBlocks   = (NN * FF / 4 + 255) / 256;
    int zero64Blocks = (NN * OO / 4 + 255) / 256;
    int scatterBlocks = (2 * EE) / 8;             // warp per (rel, edge)
    int scatter2Blocks = (2 * EE * 16 + 255) / 256;
    int gemmBlocks = (NN + 127) / 128;
    int scoreBlocks = (2 * EE * 16 + 255) / 256;

    // 5 launches, then scatter_kernel is #6 => captured by ncu -s 5 -c 1
    zero_all_kernel<<<zeroBlocks, 256>>>();                                   // 1
    deg_kernel<<<(2 * EE + 255) / 256, 256>>>(edges);                         // 2
    rdeg_kernel<<<(2 * NN + 255) / 256, 256>>>();                             // 3
    pack1_kernel<<<(384 * 128 + 255) / 256, 256>>>(Wself1, Wneigh1, b1);      // 4
    pack2_kernel<<<(128 * 128 + 255) / 256, 256>>>(Wself2, Wneigh2, b2);      // 5

    // layer 1
    scatter_kernel<<<scatterBlocks, 256>>>(x, edges);                         // 6 (profiled)
    gemm_k<1><<<gemmBlocks, 256>>>(x);                                        // 7

    // layer 2 (project-then-scatter, 64-wide)
    gemm_k<3><<<gemmBlocks, 256>>>(nullptr);                                  // 8: Y = h1 @ Wn2pack
    zero_aggs64_kernel<<<zero64Blocks, 256>>>();                              // 9
    scatter2_kernel<<<scatter2Blocks, 256>>>(edges);                          // 10
    gemm_k<2><<<gemmBlocks, 256>>>(nullptr);                                  // 11

    // scoring
    score_kernel<<<scoreBlocks, 256>>>(edges, neg, out, out_n);               // 12
}

// round 7
// speedup vs baseline: 2.8449x; 1.3611x over previous
#include <cuda_runtime.h>
#include <cuda_bf16.h>
#include <cstdint>

// Problem constants (fixed shapes from reference setup_inputs)
#define NN 50000      // nodes
#define FF 128        // F_in == H
#define OO 64         // output feature dim
#define EE 800000     // edges per relation (and neg edges)
#define NSEG (2 * NN) // (relation, node) segments
#define NB_SCAN ((NSEG + 1023) / 1024)   // 98 blocks

// ---------------- scratch (device globals; device-code access ONLY) --------
__device__ alignas(16) float g_agg0[NN * FF];      // layer1: mean 128-wide; layer2: 64-wide
__device__ alignas(16) float g_agg1[NN * FF];
__device__ alignas(16) float g_h1[NN * FF];        // layer 1 output
__device__ alignas(16) float g_Y[NN * FF];         // h1 @ [Wn2_0 | Wn2_1]
__device__ alignas(16) float g_h2[NN * OO];        // layer 2 output
__device__ alignas(16) float g_W1[384 * 128];      // packed [Wself_sum; Wn0; Wn1]
__device__ alignas(16) float g_b1[128];
__device__ alignas(16) float g_Wn2pack[128 * 128]; // [Wn2_0 | Wn2_1]
__device__ alignas(16) float g_Ws2sum[128 * 64];   // Wself2[0]+Wself2[1]
__device__ alignas(16) float g_b2[64];
// CSR structures (built once, used by both layers)
__device__ int g_deg[NSEG];
__device__ int g_off[NSEG];
__device__ int g_cursor[NSEG];
__device__ int g_bsum[NB_SCAN];
__device__ int g_csr[2 * EE];

// ---------------- CSR build -------------------------------------------------
__global__ void zero_deg_kernel() {
    int i = blockIdx.x * blockDim.x + threadIdx.x;
    if (i < NSEG) g_deg[i] = 0;
}

__global__ void deg_kernel(const int* __restrict__ edges) {
    int i = blockIdx.x * blockDim.x + threadIdx.x;
    if (i < 2 * EE) {
        int r = i / EE;
        int e = i - r * EE;
        int dst = edges[r * 2 * EE + EE + e];
        atomicAdd(&g_deg[r * NN + dst], 1);
    }
}

// block-wise exclusive scan (1024/block) producing per-block sums
__global__ void scanA_kernel() {
    __shared__ int sh[1024];
    int gid = blockIdx.x * 1024 + threadIdx.x;
    int v = (gid < NSEG) ? g_deg[gid] : 0;
    sh[threadIdx.x] = v;
    __syncthreads();
    for (int off = 1; off < 1024; off <<= 1) {
        int t = (threadIdx.x >= off) ? sh[threadIdx.x - off] : 0;
        __syncthreads();
        sh[threadIdx.x] += t;
        __syncthreads();
    }
    int incl = sh[threadIdx.x];
    if (gid < NSEG) g_off[gid] = incl - v;
    if (threadIdx.x == 1023) g_bsum[blockIdx.x] = incl;
}

__global__ void scanB_kernel() {   // single thread: 98 iterations
    if (threadIdx.x == 0 && blockIdx.x == 0) {
        int run = 0;
        for (int b = 0; b < NB_SCAN; ++b) {
            int t = g_bsum[b];
            g_bsum[b] = run;
            run += t;
        }
    }
}

__global__ void scanC_kernel() {
    int gid = blockIdx.x * blockDim.x + threadIdx.x;
    if (gid < NSEG) {
        int o = g_off[gid] + g_bsum[gid >> 10];
        g_off[gid] = o;
        g_cursor[gid] = o;
    }
}

__global__ void fill_kernel(const int* __restrict__ edges) {
    int i = blockIdx.x * blockDim.x + threadIdx.x;
    if (i < 2 * EE) {
        int r = i / EE;
        int e = i - r * EE;
        const int* ed = edges + r * 2 * EE;
        int src = ed[e];
        int dst = ed[EE + e];
        int pos = atomicAdd(&g_cursor[r * NN + dst], 1);
        g_csr[pos] = src;
    }
}

// ---------------- weight packing --------------------------------------------
__global__ void pack1_kernel(const float* __restrict__ Wself,
                             const float* __restrict__ Wneigh,
                             const float* __restrict__ b) {
    int idx = blockIdx.x * blockDim.x + threadIdx.x;
    if (idx < 384 * 128) {
        int k = idx >> 7;
        int n = idx & 127;
        float w;
        if (k < 128)      w = Wself[k * 128 + n] + Wself[128 * 128 + k * 128 + n];
        else if (k < 256) w = Wneigh[(k - 128) * 128 + n];
        else              w = Wneigh[128 * 128 + (k - 256) * 128 + n];
        g_W1[idx] = w;
    }
    if (idx < 128) g_b1[idx] = b[idx] + b[128 + idx];
}

__global__ void pack2_kernel(const float* __restrict__ Wself,
                             const float* __restrict__ Wneigh,
                             const float* __restrict__ b) {
    int idx = blockIdx.x * blockDim.x + threadIdx.x;
    if (idx < 128 * 128) {
        int k = idx >> 7;
        int n = idx & 127;
        g_Wn2pack[idx] = (n < 64) ? Wneigh[k * 64 + n]
                                  : Wneigh[128 * 64 + k * 64 + (n - 64)];
    }
    if (idx < 128 * 64) g_Ws2sum[idx] = Wself[idx] + Wself[128 * 64 + idx];
    if (idx < 64)       g_b2[idx] = b[idx] + b[64 + idx];
}

// ---------------- CSR gather (no atomics, writes means directly) ------------
// layer 1: warp per (relation, node); 128-wide rows of x
__global__ void gather1_kernel(const float* __restrict__ x) {
    int gw = (blockIdx.x * blockDim.x + threadIdx.x) >> 5;
    int lane = threadIdx.x & 31;
    if (gw >= NSEG) return;
    int r = gw >= NN;
    int node = gw - r * NN;
    int start = g_off[gw];
    int cnt = g_deg[gw];
    float4 acc = make_float4(0.f, 0.f, 0.f, 0.f);
    for (int k = 0; k < cnt; ++k) {
        int src = __ldg(&g_csr[start + k]);
        float4 v = *reinterpret_cast<const float4*>(x + (size_t)src * FF + lane * 4);
        acc.x += v.x; acc.y += v.y; acc.z += v.z; acc.w += v.w;
    }
    float sc = 1.0f / fmaxf((float)cnt, 1.0f);
    acc.x *= sc; acc.y *= sc; acc.z *= sc; acc.w *= sc;
    float* agg = r ? g_agg1 : g_agg0;
    *reinterpret_cast<float4*>(agg + (size_t)node * FF + lane * 4) = acc;
}

// layer 2: 16 lanes per (relation, node); 64-wide slices of Y
__global__ void gather2_kernel() {
    int t = blockIdx.x * blockDim.x + threadIdx.x;
    int grp = t >> 4;
    int lane = t & 15;
    if (grp >= NSEG) return;
    int r = grp >= NN;
    int node = grp - r * NN;
    int start = g_off[grp];
    int cnt = g_deg[grp];
    float4 acc = make_float4(0.f, 0.f, 0.f, 0.f);
    const float* Ysl = g_Y + r * OO;
    for (int k = 0; k < cnt; ++k) {
        int src = __ldg(&g_csr[start + k]);
        float4 v = *reinterpret_cast<const float4*>(Ysl + (size_t)src * FF + lane * 4);
        acc.x += v.x; acc.y += v.y; acc.z += v.z; acc.w += v.w;
    }
    float sc = 1.0f / fmaxf((float)cnt, 1.0f);
    acc.x *= sc; acc.y *= sc; acc.z *= sc; acc.w *= sc;
    float* agg = r ? g_agg1 : g_agg0;
    *reinterpret_cast<float4*>(agg + (size_t)node * OO + lane * 4) = acc;
}

// ---------------- GEMM core (3 modes) ---------------------------------------
// MODE 1: h1 = relu([x | mean0 | mean1] @ W1 + b1)     (K=384, N=128)
// MODE 3: Y  = h1 @ Wn2pack                            (K=128, N=128)
// MODE 2: h2 = h1 @ Ws2sum + b2 + mean0 + mean1        (K=128, N=64)
template <int MODE>
__global__ void __launch_bounds__(256) gemm_k(const float* __restrict__ x) {
    constexpr int N  = (MODE == 2) ? 64 : 128;
    constexpr int BN = N;
    constexpr int TN = N / 16;          // 8 or 4
    constexpr int BM = 128, BK = 32, TM = 8;
    constexpr int KT = (MODE == 1) ? 12 : 4;
    constexpr int M = NN;

    __shared__ alignas(16) float As[BK][BM + 4];
    __shared__ alignas(16) float Bs[BK][BN];

    const float* A0 = (MODE == 1) ? x : g_h1;
    const float* W  = (MODE == 1) ? g_W1 : ((MODE == 3) ? g_Wn2pack : g_Ws2sum);
    float* C        = (MODE == 1) ? g_h1 : ((MODE == 3) ? g_Y : g_h2);

    int tid = threadIdx.x;
    int m0 = blockIdx.x * BM;
    int tx = tid % (BN / TN);
    int ty = tid / (BN / TN);

    float acc[TM][TN];
#pragma unroll
    for (int i = 0; i < TM; i++)
#pragma unroll
        for (int j = 0; j < TN; j++) acc[i][j] = 0.f;

#pragma unroll 1
    for (int t = 0; t < KT; ++t) {
        int kg = t * BK;
        const float* Ap;
        int koff;
        if (MODE == 1) {
            int slice = kg >> 7;
            Ap = (slice == 0) ? A0 : ((slice == 1) ? g_agg0 : g_agg1);
            koff = kg & 127;
        } else {
            Ap = A0;
            koff = kg;
        }

        // A tile: 128x32 transposed into As[k][m]
#pragma unroll
        for (int i = 0; i < 4; ++i) {
            int idx = tid + i * 256;
            int row = idx >> 3;
            int c4 = idx & 7;
            float4 v = make_float4(0.f, 0.f, 0.f, 0.f);
            int gm = m0 + row;
            if (gm < M)
                v = *reinterpret_cast<const float4*>(Ap + (size_t)gm * 128 + koff + c4 * 4);
            As[c4 * 4 + 0][row] = v.x;
            As[c4 * 4 + 1][row] = v.y;
            As[c4 * 4 + 2][row] = v.z;
            As[c4 * 4 + 3][row] = v.w;
        }
        // B tile: 32 x BN
#pragma unroll
        for (int i = 0; i < BN / 32; ++i) {
            int idx = tid + i * 256;
            int kk = idx / (BN / 4);
            int n4 = idx - kk * (BN / 4);
            float4 v = *reinterpret_cast<const float4*>(W + (size_t)(kg + kk) * N + n4 * 4);
            *reinterpret_cast<float4*>(&Bs[kk][n4 * 4]) = v;
        }
        __syncthreads();

#pragma unroll
        for (int kk = 0; kk < BK; ++kk) {
            float a[TM], b[TN];
            const float4* Ar = reinterpret_cast<const float4*>(&As[kk][ty * TM]);
            float4 a0 = Ar[0], a1 = Ar[1];
            a[0] = a0.x; a[1] = a0.y; a[2] = a0.z; a[3] = a0.w;
            a[4] = a1.x; a[5] = a1.y; a[6] = a1.z; a[7] = a1.w;
            const float4* Br = reinterpret_cast<const float4*>(&Bs[kk][tx * TN]);
            float4 b0 = Br[0];
            b[0] = b0.x; b[1] = b0.y; b[2] = b0.z; b[3] = b0.w;
            if (TN == 8) {
                float4 b1 = Br[1];
                b[4] = b1.x; b[5] = b1.y; b[6] = b1.z; b[7] = b1.w;
            }
#pragma unroll
            for (int i = 0; i < TM; i++)
#pragma unroll
                for (int j = 0; j < TN; j++) acc[i][j] += a[i] * b[j];
        }
        __syncthreads();
    }

#pragma unroll
    for (int i = 0; i < TM; i++) {
        int gm = m0 + ty * TM + i;
        if (gm >= M) continue;
        if (MODE == 2) {
            float4 a0 = *reinterpret_cast<const float4*>(g_agg0 + (size_t)gm * OO + tx * 4);
            float4 a1 = *reinterpret_cast<const float4*>(g_agg1 + (size_t)gm * OO + tx * 4);
            float4 o;
            o.x = acc[i][0] + g_b2[tx * 4 + 0] + a0.x + a1.x;
            o.y = acc[i][1] + g_b2[tx * 4 + 1] + a0.y + a1.y;
            o.z = acc[i][2] + g_b2[tx * 4 + 2] + a0.z + a1.z;
            o.w = acc[i][3] + g_b2[tx * 4 + 3] + a0.w + a1.w;
            *reinterpret_cast<float4*>(g_h2 + (size_t)gm * OO + tx * 4) = o;
        } else {
#pragma unroll
            for (int j = 0; j < TN; j++) {
                int gn = tx * TN + j;
                float v = acc[i][j];
                if (MODE == 1) v = fmaxf(v + g_b1[gn], 0.f);
                C[(size_t)gm * N + gn] = v;
            }
        }
    }
}

// ---------------- edge scoring (16 lanes per edge, float4) ------------------
__global__ void score_kernel(const int* __restrict__ edges,
                             const int* __restrict__ neg,
                             float* __restrict__ out, int out_n) {
    int t = blockIdx.x * blockDim.x + threadIdx.x;
    int ge = t >> 4;
    int lane = t & 15;
    if (ge >= 2 * EE) return;
    int u, v;
    if (ge < EE) { u = edges[ge]; v = edges[EE + ge]; }
    else { int e = ge - EE; u = neg[e]; v = neg[EE + e]; }
    float4 a = *reinterpret_cast<const float4*>(g_h2 + (size_t)u * OO + lane * 4);
    float4 b = *reinterpret_cast<const float4*>(g_h2 + (size_t)v * OO + lane * 4);
    float s = a.x * b.x + a.y * b.y + a.z * b.z + a.w * b.w;
#pragma unroll
    for (int off = 8; off; off >>= 1) s += __shfl_xor_sync(0xffffffffu, s, off);
    if (lane == 0 && ge < out_n) out[ge] = s;
}

// ---------------- launch ----------------------------------------------------
extern "C" void kernel_launch(void* const* d_in, const int* in_sizes, int n_in,
                              void* d_out, int out_size) {
    // Resolve inputs by element count; positional fallback (reference order).
    const float* x = nullptr;  const int* edges = nullptr; const int* neg = nullptr;
    const float* Wneigh1 = nullptr, *Wself1 = nullptr, *b1 = nullptr;
    const float* Wneigh2 = nullptr, *Wself2 = nullptr, *b2 = nullptr;
    {
        const float* wn1 = nullptr, *ws1 = nullptr, *wn2 = nullptr, *ws2 = nullptr;
        const float* xx = nullptr, *bb1 = nullptr, *bb2 = nullptr;
        const int* ee = nullptr, *nn = nullptr;
        for (int i = 0; i < n_in; ++i) {
            long s = in_sizes[i];
            const void* p = d_in[i];
            if      (s == (long)NN * FF)       xx = (const float*)p;
            else if (s == (long)2 * 2 * EE)    ee = (const int*)p;
            else if (s == (long)2 * EE)        nn = (const int*)p;
            else if (s == (long)2 * 128 * 128) { if (!wn1) wn1 = (const float*)p; else ws1 = (const float*)p; }
            else if (s == (long)2 * 128)       bb1 = (const float*)p;
            else if (s == (long)2 * 128 * 64)  { if (!wn2) wn2 = (const float*)p; else ws2 = (const float*)p; }
            else if (s == (long)2 * 64)        bb2 = (const float*)p;
        }
        if (xx && ee && nn && wn1 && ws1 && bb1 && wn2 && ws2 && bb2) {
            x = xx; edges = ee; neg = nn;
            Wneigh1 = wn1; Wself1 = ws1; b1 = bb1;
            Wneigh2 = wn2; Wself2 = ws2; b2 = bb2;
        }
    }
    if (!x) {
        x       = (const float*)d_in[0];
        edges   = (const int*)  d_in[1];
        neg     = (const int*)  d_in[2];
        Wneigh1 = (const float*)d_in[3];
        Wself1  = (const float*)d_in[4];
        b1      = (const float*)d_in[5];
        Wneigh2 = (const float*)d_in[6];
        Wself2  = (const float*)d_in[7];
        b2      = (const float*)d_in[8];
    }
    float* out = (float*)d_out;
    int out_n = out_size;
    if (out_n > 2 * EE) out_n = 2 * EE;

    int edgeBlocks   = (2 * EE + 255) / 256;
    int segBlocks    = (NSEG + 255) / 256;
    int gather1Blocks = (NSEG * 32 + 255) / 256;
    int gather2Blocks = (NSEG * 16 + 255) / 256;
    int gemmBlocks   = (NN + 127) / 128;
    int scoreBlocks  = (2 * EE * 16 + 255) / 256;

    // CSR build (used by both layers)
    zero_deg_kernel<<<segBlocks, 256>>>();
    deg_kernel<<<edgeBlocks, 256>>>(edges);
    scanA_kernel<<<NB_SCAN, 1024>>>();
    scanB_kernel<<<1, 32>>>();
    scanC_kernel<<<segBlocks, 256>>>();
    fill_kernel<<<edgeBlocks, 256>>>(edges);

    // packed weights
    pack1_kernel<<<(384 * 128 + 255) / 256, 256>>>(Wself1, Wneigh1, b1);
    pack2_kernel<<<(128 * 128 + 255) / 256, 256>>>(Wself2, Wneigh2, b2);

    // layer 1: gather means, fused GEMM
    gather1_kernel<<<gather1Blocks, 256>>>(x);
    gemm_k<1><<<gemmBlocks, 256>>>(x);

    // layer 2: project-then-gather (64-wide)
    gemm_k<3><<<gemmBlocks, 256>>>(nullptr);
    gather2_kernel<<<gather2Blocks, 256>>>();
    gemm_k<2><<<gemmBlocks, 256>>>(nullptr);

    // scoring
    score_kernel<<<scoreBlocks, 256>>>(edges, neg, out, out_n);
}

// round 8
// speedup vs baseline: 2.9450x; 1.0352x over previous
#include <cuda_runtime.h>
#include <cuda_bf16.h>
#include <cstdint>

// Problem constants (fixed shapes from reference setup_inputs)
#define NN 50000      // nodes
#define FF 128        // F_in == H
#define OO 64         // output feature dim
#define EE 800000     // edges per relation (and neg edges)
#define NSEG (2 * NN) // (relation, node) segments
#define NB_SCAN ((NSEG + 1023) / 1024)   // 98 blocks

// ---------------- scratch (device globals; device-code access ONLY) --------
__device__ alignas(16) float g_agg0[NN * FF];      // layer1: mean 128-wide; layer2: 64-wide
__device__ alignas(16) float g_agg1[NN * FF];
__device__ alignas(16) float g_h1[NN * FF];        // layer 1 output
__device__ alignas(16) float g_Y[NN * FF];         // h1 @ [Wn2_0 | Wn2_1]
__device__ alignas(16) float g_h2[NN * OO];        // layer 2 output
__device__ alignas(16) float g_W1[384 * 128];      // packed [Wself_sum; Wn0; Wn1]
__device__ alignas(16) float g_b1[128];
__device__ alignas(16) float g_Wn2pack[128 * 128]; // [Wn2_0 | Wn2_1]
__device__ alignas(16) float g_Ws2sum[128 * 64];   // Wself2[0]+Wself2[1]
__device__ alignas(16) float g_b2[64];
// CSR structures (built once, used by both layers)
__device__ int g_deg[NSEG];
__device__ int g_off[NSEG];
__device__ int g_cursor[NSEG];
__device__ int g_bsum[NB_SCAN];
__device__ int g_csr[2 * EE];

// ---------------- packed fp32x2 helpers (Blackwell FFMA2 path) --------------
__device__ __forceinline__ unsigned long long dup2(float a) {
    unsigned long long r;
    asm("mov.b64 %0, {%1, %1};" : "=l"(r) : "f"(a));
    return r;
}
__device__ __forceinline__ unsigned long long fma2(unsigned long long a,
                                                   unsigned long long b,
                                                   unsigned long long c) {
    unsigned long long d;
    asm("fma.rn.f32x2 %0, %1, %2, %3;" : "=l"(d) : "l"(a), "l"(b), "l"(c));
    return d;
}
__device__ __forceinline__ void unpack2(unsigned long long p, float& lo, float& hi) {
    asm("mov.b64 {%0, %1}, %2;" : "=f"(lo), "=f"(hi) : "l"(p));
}

// ---------------- CSR build -------------------------------------------------
__global__ void zero_deg_kernel() {
    int i = blockIdx.x * blockDim.x + threadIdx.x;
    if (i < NSEG) g_deg[i] = 0;
}

__global__ void deg_kernel(const int* __restrict__ edges) {
    int i = blockIdx.x * blockDim.x + threadIdx.x;
    if (i < 2 * EE) {
        int r = i / EE;
        int e = i - r * EE;
        int dst = edges[r * 2 * EE + EE + e];
        atomicAdd(&g_deg[r * NN + dst], 1);
    }
}

// block-wise exclusive scan (1024/block) producing per-block sums
__global__ void scanA_kernel() {
    __shared__ int sh[1024];
    int gid = blockIdx.x * 1024 + threadIdx.x;
    int v = (gid < NSEG) ? g_deg[gid] : 0;
    sh[threadIdx.x] = v;
    __syncthreads();
    for (int off = 1; off < 1024; off <<= 1) {
        int t = (threadIdx.x >= off) ? sh[threadIdx.x - off] : 0;
        __syncthreads();
        sh[threadIdx.x] += t;
        __syncthreads();
    }
    int incl = sh[threadIdx.x];
    if (gid < NSEG) g_off[gid] = incl - v;
    if (threadIdx.x == 1023) g_bsum[blockIdx.x] = incl;
}

// parallel exclusive scan over NB_SCAN block sums (single block)
__global__ void scanB_kernel() {
    __shared__ int sh[NB_SCAN];
    int t = threadIdx.x;
    int v0 = 0;
    if (t < NB_SCAN) { v0 = g_bsum[t]; sh[t] = v0; }
    __syncthreads();
    for (int off = 1; off < NB_SCAN; off <<= 1) {
        int v = (t >= off && t < NB_SCAN) ? sh[t - off] : 0;
        __syncthreads();
        if (t < NB_SCAN) sh[t] += v;
        __syncthreads();
    }
    if (t < NB_SCAN) g_bsum[t] = sh[t] - v0;   // exclusive
}

__global__ void scanC_kernel() {
    int gid = blockIdx.x * blockDim.x + threadIdx.x;
    if (gid < NSEG) {
        int o = g_off[gid] + g_bsum[gid >> 10];
        g_off[gid] = o;
        g_cursor[gid] = o;
    }
}

__global__ void fill_kernel(const int* __restrict__ edges) {
    int i = blockIdx.x * blockDim.x + threadIdx.x;
    if (i < 2 * EE) {
        int r = i / EE;
        int e = i - r * EE;
        const int* ed = edges + r * 2 * EE;
        int src = ed[e];
        int dst = ed[EE + e];
        int pos = atomicAdd(&g_cursor[r * NN + dst], 1);
        g_csr[pos] = src;
    }
}

// ---------------- weight packing --------------------------------------------
__global__ void pack1_kernel(const float* __restrict__ Wself,
                             const float* __restrict__ Wneigh,
                             const float* __restrict__ b) {
    int idx = blockIdx.x * blockDim.x + threadIdx.x;
    if (idx < 384 * 128) {
        int k = idx >> 7;
        int n = idx & 127;
        float w;
        if (k < 128)      w = Wself[k * 128 + n] + Wself[128 * 128 + k * 128 + n];
        else if (k < 256) w = Wneigh[(k - 128) * 128 + n];
        else              w = Wneigh[128 * 128 + (k - 256) * 128 + n];
        g_W1[idx] = w;
    }
    if (idx < 128) g_b1[idx] = b[idx] + b[128 + idx];
}

__global__ void pack2_kernel(const float* __restrict__ Wself,
                             const float* __restrict__ Wneigh,
                             const float* __restrict__ b) {
    int idx = blockIdx.x * blockDim.x + threadIdx.x;
    if (idx < 128 * 128) {
        int k = idx >> 7;
        int n = idx & 127;
        g_Wn2pack[idx] = (n < 64) ? Wneigh[k * 64 + n]
                                  : Wneigh[128 * 64 + k * 64 + (n - 64)];
    }
    if (idx < 128 * 64) g_Ws2sum[idx] = Wself[idx] + Wself[128 * 64 + idx];
    if (idx < 64)       g_b2[idx] = b[idx] + b[64 + idx];
}

// ---------------- CSR gather (no atomics, writes means directly) ------------
// layer 1: warp per (relation, node); 128-wide rows of x
__global__ void gather1_kernel(const float* __restrict__ x) {
    int gw = (blockIdx.x * blockDim.x + threadIdx.x) >> 5;
    int lane = threadIdx.x & 31;
    if (gw >= NSEG) return;
    int r = gw >= NN;
    int node = gw - r * NN;
    int start = g_off[gw];
    int cnt = g_deg[gw];
    float4 acc = make_float4(0.f, 0.f, 0.f, 0.f);
    for (int k = 0; k < cnt; ++k) {
        int src = __ldg(&g_csr[start + k]);
        float4 v = *reinterpret_cast<const float4*>(x + (size_t)src * FF + lane * 4);
        acc.x += v.x; acc.y += v.y; acc.z += v.z; acc.w += v.w;
    }
    float sc = 1.0f / fmaxf((float)cnt, 1.0f);
    acc.x *= sc; acc.y *= sc; acc.z *= sc; acc.w *= sc;
    float* agg = r ? g_agg1 : g_agg0;
    *reinterpret_cast<float4*>(agg + (size_t)node * FF + lane * 4) = acc;
}

// layer 2: 16 lanes per (relation, node); 64-wide slices of Y
__global__ void gather2_kernel() {
    int t = blockIdx.x * blockDim.x + threadIdx.x;
    int grp = t >> 4;
    int lane = t & 15;
    if (grp >= NSEG) return;
    int r = grp >= NN;
    int node = grp - r * NN;
    int start = g_off[grp];
    int cnt = g_deg[grp];
    float4 acc = make_float4(0.f, 0.f, 0.f, 0.f);
    const float* Ysl = g_Y + r * OO;
    for (int k = 0; k < cnt; ++k) {
        int src = __ldg(&g_csr[start + k]);
        float4 v = *reinterpret_cast<const float4*>(Ysl + (size_t)src * FF + lane * 4);
        acc.x += v.x; acc.y += v.y; acc.z += v.z; acc.w += v.w;
    }
    float sc = 1.0f / fmaxf((float)cnt, 1.0f);
    acc.x *= sc; acc.y *= sc; acc.z *= sc; acc.w *= sc;
    float* agg = r ? g_agg1 : g_agg0;
    *reinterpret_cast<float4*>(agg + (size_t)node * OO + lane * 4) = acc;
}

// ---------------- GEMM core (3 modes), packed-f32x2 mainloop ----------------
// MODE 1: h1 = relu([x | mean0 | mean1] @ W1 + b1)     (K=384, N=128)
// MODE 3: Y  = h1 @ Wn2pack                            (K=128, N=128)
// MODE 2: h2 = h1 @ Ws2sum + b2 + mean0 + mean1        (K=128, N=64)
template <int MODE>
__global__ void __launch_bounds__(256) gemm_k(const float* __restrict__ x) {
    constexpr int N  = (MODE == 2) ? 64 : 128;
    constexpr int BN = N;
    constexpr int TN = N / 16;          // 8 or 4
    constexpr int TN2 = TN / 2;         // packed accumulators along n
    constexpr int BM = 128, BK = 32, TM = 8;
    constexpr int KT = (MODE == 1) ? 12 : 4;
    constexpr int M = NN;

    __shared__ alignas(16) float As[BK][BM + 4];
    __shared__ alignas(16) float Bs[BK][BN];

    const float* A0 = (MODE == 1) ? x : g_h1;
    const float* W  = (MODE == 1) ? g_W1 : ((MODE == 3) ? g_Wn2pack : g_Ws2sum);
    float* C        = (MODE == 1) ? g_h1 : ((MODE == 3) ? g_Y : g_h2);

    int tid = threadIdx.x;
    int m0 = blockIdx.x * BM;
    int tx = tid % (BN / TN);
    int ty = tid / (BN / TN);

    unsigned long long acc2[TM][TN2];
#pragma unroll
    for (int i = 0; i < TM; i++)
#pragma unroll
        for (int j = 0; j < TN2; j++) acc2[i][j] = 0ull;

#pragma unroll 1
    for (int t = 0; t < KT; ++t) {
        int kg = t * BK;
        const float* Ap;
        int koff;
        if (MODE == 1) {
            int slice = kg >> 7;
            Ap = (slice == 0) ? A0 : ((slice == 1) ? g_agg0 : g_agg1);
            koff = kg & 127;
        } else {
            Ap = A0;
            koff = kg;
        }

        // A tile: 128x32 transposed into As[k][m]
#pragma unroll
        for (int i = 0; i < 4; ++i) {
            int idx = tid + i * 256;
            int row = idx >> 3;
            int c4 = idx & 7;
            float4 v = make_float4(0.f, 0.f, 0.f, 0.f);
            int gm = m0 + row;
            if (gm < M)
                v = *reinterpret_cast<const float4*>(Ap + (size_t)gm * 128 + koff + c4 * 4);
            As[c4 * 4 + 0][row] = v.x;
            As[c4 * 4 + 1][row] = v.y;
            As[c4 * 4 + 2][row] = v.z;
            As[c4 * 4 + 3][row] = v.w;
        }
        // B tile: 32 x BN
#pragma unroll
        for (int i = 0; i < BN / 32; ++i) {
            int idx = tid + i * 256;
            int kk = idx / (BN / 4);
            int n4 = idx - kk * (BN / 4);
            float4 v = *reinterpret_cast<const float4*>(W + (size_t)(kg + kk) * N + n4 * 4);
            *reinterpret_cast<float4*>(&Bs[kk][n4 * 4]) = v;
        }
        __syncthreads();

#pragma unroll
        for (int kk = 0; kk < BK; ++kk) {
            // A fragment: 8 floats, duplicated into packed form
            const float4* Ar = reinterpret_cast<const float4*>(&As[kk][ty * TM]);
            float4 a0 = Ar[0], a1 = Ar[1];
            unsigned long long ad[TM];
            ad[0] = dup2(a0.x); ad[1] = dup2(a0.y); ad[2] = dup2(a0.z); ad[3] = dup2(a0.w);
            ad[4] = dup2(a1.x); ad[5] = dup2(a1.y); ad[6] = dup2(a1.z); ad[7] = dup2(a1.w);
            // B fragment: TN floats as TN/2 packed pairs (adjacent n, direct 64-bit view)
            const double2* Br = reinterpret_cast<const double2*>(&Bs[kk][tx * TN]);
            unsigned long long bp[TN2];
            {
                double2 bq = Br[0];
                bp[0] = __double_as_longlong(bq.x);
                bp[1] = __double_as_longlong(bq.y);
                if (TN == 8) {
                    double2 bq1 = Br[1];
                    bp[2] = __double_as_longlong(bq1.x);
                    bp[3] = __double_as_longlong(bq1.y);
                }
            }
#pragma unroll
            for (int i = 0; i < TM; i++)
#pragma unroll
                for (int j = 0; j < TN2; j++)
                    acc2[i][j] = fma2(ad[i], bp[j], acc2[i][j]);
        }
        __syncthreads();
    }

#pragma unroll
    for (int i = 0; i < TM; i++) {
        int gm = m0 + ty * TM + i;
        if (gm >= M) continue;
        float accs[TN];
#pragma unroll
        for (int j = 0; j < TN2; j++) unpack2(acc2[i][j], accs[2 * j], accs[2 * j + 1]);
        if (MODE == 2) {
            float4 a0 = *reinterpret_cast<const float4*>(g_agg0 + (size_t)gm * OO + tx * 4);
            float4 a1 = *reinterpret_cast<const float4*>(g_agg1 + (size_t)gm * OO + tx * 4);
            float4 o;
            o.x = accs[0] + g_b2[tx * 4 + 0] + a0.x + a1.x;
            o.y = accs[1] + g_b2[tx * 4 + 1] + a0.y + a1.y;
            o.z = accs[2] + g_b2[tx * 4 + 2] + a0.z + a1.z;
            o.w = accs[3] + g_b2[tx * 4 + 3] + a0.w + a1.w;
            *reinterpret_cast<float4*>(g_h2 + (size_t)gm * OO + tx * 4) = o;
        } else {
#pragma unroll
            for (int j = 0; j < TN; j++) {
                int gn = tx * TN + j;
                float v = accs[j];
                if (MODE == 1) v = fmaxf(v + g_b1[gn], 0.f);
                C[(size_t)gm * N + gn] = v;
            }
        }
    }
}

// ---------------- edge scoring (16 lanes per edge, float4) ------------------
__global__ void score_kernel(const int* __restrict__ edges,
                             const int* __restrict__ neg,
                             float* __restrict__ out, int out_n) {
    int t = blockIdx.x * blockDim.x + threadIdx.x;
    int ge = t >> 4;
    int lane = t & 15;
    if (ge >= 2 * EE) return;
    int u, v;
    if (ge < EE) { u = edges[ge]; v = edges[EE + ge]; }
    else { int e = ge - EE; u = neg[e]; v = neg[EE + e]; }
    float4 a = *reinterpret_cast<const float4*>(g_h2 + (size_t)u * OO + lane * 4);
    float4 b = *reinterpret_cast<const float4*>(g_h2 + (size_t)v * OO + lane * 4);
    float s = a.x * b.x + a.y * b.y + a.z * b.z + a.w * b.w;
#pragma unroll
    for (int off = 8; off; off >>= 1) s += __shfl_xor_sync(0xffffffffu, s, off);
    if (lane == 0 && ge < out_n) out[ge] = s;
}

// ---------------- launch ----------------------------------------------------
extern "C" void kernel_launch(void* const* d_in, const int* in_sizes, int n_in,
                              void* d_out, int out_size) {
    // Resolve inputs by element count; positional fallback (reference order).
    const float* x = nullptr;  const int* edges = nullptr; const int* neg = nullptr;
    const float* Wneigh1 = nullptr, *Wself1 = nullptr, *b1 = nullptr;
    const float* Wneigh2 = nullptr, *Wself2 = nullptr, *b2 = nullptr;
    {
        const float* wn1 = nullptr, *ws1 = nullptr, *wn2 = nullptr, *ws2 = nullptr;
        const float* xx = nullptr, *bb1 = nullptr, *bb2 = nullptr;
        const int* ee = nullptr, *nn = nullptr;
        for (int i = 0; i < n_in; ++i) {
            long s = in_sizes[i];
            const void* p = d_in[i];
            if      (s == (long)NN * FF)       xx = (const float*)p;
            else if (s == (long)2 * 2 * EE)    ee = (const int*)p;
            else if (s == (long)2 * EE)        nn = (const int*)p;
            else if (s == (long)2 * 128 * 128) { if (!wn1) wn1 = (const float*)p; else ws1 = (const float*)p; }
            else if (s == (long)2 * 128)       bb1 = (const float*)p;
            else if (s == (long)2 * 128 * 64)  { if (!wn2) wn2 = (const float*)p; else ws2 = (const float*)p; }
            else if (s == (long)2 * 64)        bb2 = (const float*)p;
        }
        if (xx && ee && nn && wn1 && ws1 && bb1 && wn2 && ws2 && bb2) {
            x = xx; edges = ee; neg = nn;
            Wneigh1 = wn1; Wself1 = ws1; b1 = bb1;
            Wneigh2 = wn2; Wself2 = ws2; b2 = bb2;
        }
    }
    if (!x) {
        x       = (const float*)d_in[0];
        edges   = (const int*)  d_in[1];
        neg     = (const int*)  d_in[2];
        Wneigh1 = (const float*)d_in[3];
        Wself1  = (const float*)d_in[4];
        b1      = (const float*)d_in[5];
        Wneigh2 = (const float*)d_in[6];
        Wself2  = (const float*)d_in[7];
        b2      = (const float*)d_in[8];
    }
    float* out = (float*)d_out;
    int out_n = out_size;
    if (out_n > 2 * EE) out_n = 2 * EE;

    int edgeBlocks    = (2 * EE + 255) / 256;
    int segBlocks     = (NSEG + 255) / 256;
    int gather1Blocks = (NSEG * 32 + 255) / 256;
    int gather2Blocks = (NSEG * 16 + 255) / 256;
    int gemmBlocks    = (NN + 127) / 128;
    int scoreBlocks   = (2 * EE * 16 + 255) / 256;

    // CSR build (used by both layers)
    zero_deg_kernel<<<segBlocks, 256>>>();
    deg_kernel<<<edgeBlocks, 256>>>(edges);
    scanA_kernel<<<NB_SCAN, 1024>>>();
    scanB_kernel<<<1, 128>>>();
    scanC_kernel<<<segBlocks, 256>>>();
    fill_kernel<<<edgeBlocks, 256>>>(edges);

    // packed weights
    pack1_kernel<<<(384 * 128 + 255) / 256, 256>>>(Wself1, Wneigh1, b1);
    pack2_kernel<<<(128 * 128 + 255) / 256, 256>>>(Wself2, Wneigh2, b2);

    // layer 1: gather means, fused GEMM
    gather1_kernel<<<gather1Blocks, 256>>>(x);
    gemm_k<1><<<gemmBlocks, 256>>>(x);

    // layer 2: project-then-gather (64-wide)
    gemm_k<3><<<gemmBlocks, 256>>>(nullptr);
    gather2_kernel<<<gather2Blocks, 256>>>();
    gemm_k<2><<<gemmBlocks, 256>>>(nullptr);

    // scoring
    score_kernel<<<scoreBlocks, 256>>>(edges, neg, out, out_n);
}